// round 1
// baseline (speedup 1.0000x reference)
#include <cuda_runtime.h>

// ---------------------------------------------------------------------------
// PairWiseCrossAttention  (B=8, N=1024, D=768, H=12, HD=64)
//   q1 = heads(x1 @ Wq^T); k = heads([x1;x2] @ Wk^T); v = heads([x1;x2] @ Wv^T)
//   ctx = softmax(q1 k^T / 8) v ;  out = ctx @ Wo^T + bo
// Round 0: full fp32 baseline. GEMMs: tiled 128x128x16 SGEMM with fused
// head-layout epilogue. Attention: fused flash-style, online softmax,
// register-resident O accumulators.
// ---------------------------------------------------------------------------

#define Bsz   8
#define Ntok  1024
#define Dmod  768
#define Hn    12
#define HDim  64
#define N2    2048
#define MROWS (Bsz * Ntok)      // 8192

// Scratch (device globals: allocation-free per harness rules)
__device__ float g_Q  [Bsz * Hn * Ntok * HDim];   //  25 MB  (B,H,N,64)
__device__ float g_K  [Bsz * Hn * N2   * HDim];   //  50 MB  (B,H,2N,64)
__device__ float g_V  [Bsz * Hn * N2   * HDim];   //  50 MB
__device__ float g_ctx[Bsz * Ntok * Dmod];        //  25 MB  (B,N,D)

// ---------------------------------------------------------------------------
// GEMM: C = A @ W^T (+ bias).  A: (M,768) row-major, W: (768,768) row-major.
// mode 0: A = g_ctx, write Cout[m*768+n] + bias   (final projection)
// mode 1: A = A0 (x1),      write g_Q head layout
// mode 2: A = [A0;A1],      write g_K head layout (seq = tok or N+tok)
// mode 3: A = [A0;A1],      write g_V head layout
// ---------------------------------------------------------------------------
#define BM 128
#define BN 128
#define BK 16

__global__ __launch_bounds__(256)
void gemm_xwT(const float* __restrict__ A0, const float* __restrict__ A1,
              const float* __restrict__ W,  const float* __restrict__ bias,
              float* __restrict__ Cout, int mode)
{
    __shared__ float As[BK][BM];
    __shared__ float Bs[BK][BN];

    const int tid = threadIdx.x;
    const int m0  = blockIdx.y * BM;
    const int n0  = blockIdx.x * BN;

    const float* A = (mode == 0) ? g_ctx : A0;
    int mrow = m0;
    if ((mode == 2 || mode == 3) && m0 >= MROWS) { A = A1; mrow = m0 - MROWS; }

    const int lr = tid >> 1;          // 0..127
    const int lc = (tid & 1) * 8;     // 0 or 8
    const int ty = tid >> 4;          // 0..15
    const int tx = tid & 15;          // 0..15

    float acc[8][8];
#pragma unroll
    for (int i = 0; i < 8; ++i)
#pragma unroll
        for (int j = 0; j < 8; ++j) acc[i][j] = 0.f;

    for (int k0 = 0; k0 < Dmod; k0 += BK) {
        float4 a0 = *(const float4*)(A + (size_t)(mrow + lr) * Dmod + k0 + lc);
        float4 a1 = *(const float4*)(A + (size_t)(mrow + lr) * Dmod + k0 + lc + 4);
        float4 b0 = *(const float4*)(W + (size_t)(n0   + lr) * Dmod + k0 + lc);
        float4 b1 = *(const float4*)(W + (size_t)(n0   + lr) * Dmod + k0 + lc + 4);
        __syncthreads();
        As[lc + 0][lr] = a0.x; As[lc + 1][lr] = a0.y;
        As[lc + 2][lr] = a0.z; As[lc + 3][lr] = a0.w;
        As[lc + 4][lr] = a1.x; As[lc + 5][lr] = a1.y;
        As[lc + 6][lr] = a1.z; As[lc + 7][lr] = a1.w;
        Bs[lc + 0][lr] = b0.x; Bs[lc + 1][lr] = b0.y;
        Bs[lc + 2][lr] = b0.z; Bs[lc + 3][lr] = b0.w;
        Bs[lc + 4][lr] = b1.x; Bs[lc + 5][lr] = b1.y;
        Bs[lc + 6][lr] = b1.z; Bs[lc + 7][lr] = b1.w;
        __syncthreads();

#pragma unroll
        for (int kk = 0; kk < BK; ++kk) {
            float af[8], bf[8];
            *(float4*)&af[0] = *(const float4*)&As[kk][ty * 4];
            *(float4*)&af[4] = *(const float4*)&As[kk][64 + ty * 4];
            *(float4*)&bf[0] = *(const float4*)&Bs[kk][tx * 4];
            *(float4*)&bf[4] = *(const float4*)&Bs[kk][64 + tx * 4];
#pragma unroll
            for (int i = 0; i < 8; ++i)
#pragma unroll
                for (int j = 0; j < 8; ++j) acc[i][j] += af[i] * bf[j];
        }
    }

#pragma unroll
    for (int ii = 0; ii < 8; ++ii) {
        int ml = (ii < 4) ? (ty * 4 + ii) : (64 + ty * 4 + ii - 4);
        int gm = m0 + ml;
#pragma unroll
        for (int jj = 0; jj < 8; ++jj) {
            int nl = (jj < 4) ? (tx * 4 + jj) : (64 + tx * 4 + jj - 4);
            int gn = n0 + nl;
            float v = acc[ii][jj];
            if (mode == 0) {
                Cout[(size_t)gm * Dmod + gn] = v + bias[gn];
            } else {
                int hh = gn >> 6, dd = gn & 63;
                if (mode == 1) {
                    int b = gm >> 10, tok = gm & 1023;
                    g_Q[(((size_t)(b * Hn + hh)) * Ntok + tok) * HDim + dd] = v;
                } else {
                    int b, seq;
                    if (gm < MROWS) { b = gm >> 10; seq = gm & 1023; }
                    else { int m2 = gm - MROWS; b = m2 >> 10; seq = Ntok + (m2 & 1023); }
                    float* dst = (mode == 2) ? g_K : g_V;
                    dst[(((size_t)(b * Hn + hh)) * N2 + seq) * HDim + dd] = v;
                }
            }
        }
    }
}

// ---------------------------------------------------------------------------
// Fused attention. grid = (N/64, B*H), block = 256.
// 4 threads per query row; thread sub s owns columns c = s + 4i (i=0..15)
// of each 64-wide K tile (stride-65 smem rows -> conflict-free broadcasts).
// Online softmax; O[64] per-thread partial accumulators reduced over the
// 4 sub-threads at the end.
// ---------------------------------------------------------------------------
__global__ __launch_bounds__(256)
void attn_kernel()
{
    __shared__ float Qs [64][65];
    __shared__ float KVs[64][65];

    const int t   = threadIdx.x;
    const int row = t >> 2;
    const int sub = t & 3;
    const int q0  = blockIdx.x * 64;
    const int bh  = blockIdx.y;
    const int b   = bh / Hn;
    const int h   = bh - b * Hn;

    const float* Qg = g_Q + ((size_t)bh * Ntok + q0) * HDim;
    const float* Kg = g_K + (size_t)bh * N2 * HDim;
    const float* Vg = g_V + (size_t)bh * N2 * HDim;

    for (int i = t; i < 64 * 64; i += 256) {
        int r = i >> 6, c = i & 63;
        Qs[r][c] = Qg[r * HDim + c] * 0.125f;    // fold in 1/sqrt(64)
    }

    float m = -1e30f, l = 0.f;
    float O[64];
#pragma unroll
    for (int d = 0; d < 64; ++d) O[d] = 0.f;

    for (int k0 = 0; k0 < N2; k0 += 64) {
        __syncthreads();                          // prior tile reads done (+Q load, iter 0)
        for (int i = t; i < 64 * 64; i += 256) {
            int r = i >> 6, c = i & 63;
            KVs[r][c] = Kg[(k0 + r) * HDim + c];
        }
        __syncthreads();

        float S[16];
#pragma unroll
        for (int i = 0; i < 16; ++i) S[i] = 0.f;
#pragma unroll 8
        for (int d = 0; d < 64; ++d) {
            float qd = Qs[row][d];
#pragma unroll
            for (int i = 0; i < 16; ++i) S[i] += qd * KVs[sub + 4 * i][d];
        }

        float mt = S[0];
#pragma unroll
        for (int i = 1; i < 16; ++i) mt = fmaxf(mt, S[i]);
        mt = fmaxf(mt, __shfl_xor_sync(0xffffffffu, mt, 1));
        mt = fmaxf(mt, __shfl_xor_sync(0xffffffffu, mt, 2));
        float mnew  = fmaxf(m, mt);
        float alpha = __expf(m - mnew);
        float ls = 0.f;
#pragma unroll
        for (int i = 0; i < 16; ++i) { S[i] = __expf(S[i] - mnew); ls += S[i]; }
        ls += __shfl_xor_sync(0xffffffffu, ls, 1);
        ls += __shfl_xor_sync(0xffffffffu, ls, 2);
        l = l * alpha + ls;
        m = mnew;
#pragma unroll
        for (int d = 0; d < 64; ++d) O[d] *= alpha;

        __syncthreads();                          // K reads done; reuse buffer for V
        for (int i = t; i < 64 * 64; i += 256) {
            int r = i >> 6, c = i & 63;
            KVs[r][c] = Vg[(k0 + r) * HDim + c];
        }
        __syncthreads();

#pragma unroll
        for (int i = 0; i < 16; ++i) {
            float p = S[i];
            const float* vr = &KVs[sub + 4 * i][0];
#pragma unroll
            for (int d = 0; d < 64; ++d) O[d] += p * vr[d];
        }
    }

#pragma unroll
    for (int d = 0; d < 64; ++d) {
        O[d] += __shfl_xor_sync(0xffffffffu, O[d], 1);
        O[d] += __shfl_xor_sync(0xffffffffu, O[d], 2);
    }
    float inv = 1.f / l;
    float* dst = g_ctx + ((size_t)(b * Ntok + q0 + row)) * Dmod + h * HDim + sub * 16;
#pragma unroll
    for (int j = 0; j < 16; ++j) dst[j] = O[sub * 16 + j] * inv;
}

// ---------------------------------------------------------------------------
extern "C" void kernel_launch(void* const* d_in, const int* in_sizes, int n_in,
                              void* d_out, int out_size)
{
    const float* x1 = (const float*)d_in[0];
    const float* x2 = (const float*)d_in[1];
    const float* Wq = (const float*)d_in[2];
    const float* Wk = (const float*)d_in[3];
    const float* Wv = (const float*)d_in[4];
    const float* Wo = (const float*)d_in[5];
    const float* bo = (const float*)d_in[6];
    float* out = (float*)d_out;

    dim3 blk(256);
    dim3 gq (Dmod / BN, MROWS / BM);        // (6, 64)
    dim3 gkv(Dmod / BN, 2 * MROWS / BM);    // (6, 128)

    gemm_xwT<<<gq,  blk>>>(x1, nullptr, Wq, nullptr, nullptr, 1);   // Q
    gemm_xwT<<<gkv, blk>>>(x1, x2,      Wk, nullptr, nullptr, 2);   // K (concat)
    gemm_xwT<<<gkv, blk>>>(x1, x2,      Wv, nullptr, nullptr, 3);   // V (concat)
    attn_kernel<<<dim3(Ntok / 64, Bsz * Hn), 256>>>();              // ctx
    gemm_xwT<<<gq,  blk>>>(nullptr, nullptr, Wo, bo, out, 0);       // out proj
}

// round 2
// speedup vs baseline: 4.6205x; 4.6205x over previous
#include <cuda_runtime.h>

// ---------------------------------------------------------------------------
// PairWiseCrossAttention (B=8, N=1024, D=768, H=12, HD=64) — Round 2:
// everything on tensor cores via mma.sync.m16n8k8 TF32.
// ---------------------------------------------------------------------------

#define Bsz   8
#define Ntok  1024
#define Dmod  768
#define Hn    12
#define HDim  64
#define N2    2048
#define MROWS (Bsz * Ntok)      // 8192

__device__ float g_Q  [Bsz * Hn * Ntok * HDim];
__device__ float g_K  [Bsz * Hn * N2   * HDim];
__device__ float g_V  [Bsz * Hn * N2   * HDim];
__device__ float g_ctx[Bsz * Ntok * Dmod];

__device__ __forceinline__ unsigned f2tf(float x) {
    unsigned u;
    asm("cvt.rna.tf32.f32 %0, %1;" : "=r"(u) : "f"(x));
    return u;
}

__device__ __forceinline__ void mma_tf32(float* c, const unsigned* a, const unsigned* b) {
    asm volatile("mma.sync.aligned.m16n8k8.row.col.f32.tf32.tf32.f32 "
        "{%0,%1,%2,%3},{%4,%5,%6,%7},{%8,%9},{%0,%1,%2,%3};"
        : "+f"(c[0]), "+f"(c[1]), "+f"(c[2]), "+f"(c[3])
        : "r"(a[0]), "r"(a[1]), "r"(a[2]), "r"(a[3]), "r"(b[0]), "r"(b[1]));
}

// ---------------------------------------------------------------------------
// GEMM: C = A @ W^T (+bias). 128x128 block tile, BK=32, 8 warps (64x32 each).
// mode 0: A=g_ctx -> Cout + bias ; 1: x1 -> g_Q heads ; 2/3: [x1;x2] -> g_K/g_V
// ---------------------------------------------------------------------------
#define GBM 128
#define GBN 128
#define GBK 32
#define GSTR 36   // smem row stride (uints): 4g+t bank pattern, conflict-free frags

__global__ __launch_bounds__(256)
void gemm_tf32(const float* __restrict__ A0, const float* __restrict__ A1,
               const float* __restrict__ W,  const float* __restrict__ bias,
               float* __restrict__ Cout, int mode)
{
    __shared__ unsigned As[GBM][GSTR];
    __shared__ unsigned Bs[GBN][GSTR];

    const int tid  = threadIdx.x;
    const int lane = tid & 31, warp = tid >> 5;
    const int g = lane >> 2, tq = lane & 3;
    const int wm = warp >> 2, wn = warp & 3;          // 2 x 4 warp grid
    const int m0 = blockIdx.y * GBM, n0 = blockIdx.x * GBN;

    const float* A = (mode == 0) ? g_ctx : A0;
    int mrow = m0;
    if ((mode == 2 || mode == 3) && m0 >= MROWS) { A = A1; mrow = m0 - MROWS; }

    const int lr  = tid >> 1;          // 0..127
    const int lkq = (tid & 1) * 16;    // 0 or 16

    float acc[4][4][4];
#pragma unroll
    for (int i = 0; i < 4; ++i)
#pragma unroll
        for (int j = 0; j < 4; ++j)
#pragma unroll
            for (int c = 0; c < 4; ++c) acc[i][j][c] = 0.f;

    float4 pa[4], pb[4];
#pragma unroll
    for (int u = 0; u < 4; ++u) {
        pa[u] = *(const float4*)(A + (size_t)(mrow + lr) * Dmod + lkq + 4 * u);
        pb[u] = *(const float4*)(W + (size_t)(n0   + lr) * Dmod + lkq + 4 * u);
    }

    for (int k0 = 0; k0 < Dmod; k0 += GBK) {
        __syncthreads();
#pragma unroll
        for (int u = 0; u < 4; ++u) {
            uint4 wa = { f2tf(pa[u].x), f2tf(pa[u].y), f2tf(pa[u].z), f2tf(pa[u].w) };
            uint4 wb = { f2tf(pb[u].x), f2tf(pb[u].y), f2tf(pb[u].z), f2tf(pb[u].w) };
            *(uint4*)&As[lr][lkq + 4 * u] = wa;
            *(uint4*)&Bs[lr][lkq + 4 * u] = wb;
        }
        __syncthreads();

        if (k0 + GBK < Dmod) {
#pragma unroll
            for (int u = 0; u < 4; ++u) {
                pa[u] = *(const float4*)(A + (size_t)(mrow + lr) * Dmod + k0 + GBK + lkq + 4 * u);
                pb[u] = *(const float4*)(W + (size_t)(n0   + lr) * Dmod + k0 + GBK + lkq + 4 * u);
            }
        }

#pragma unroll
        for (int ks = 0; ks < 4; ++ks) {
            unsigned af[4][4], bf[4][2];
#pragma unroll
            for (int mi = 0; mi < 4; ++mi) {
                int r = wm * 64 + 16 * mi;
                af[mi][0] = As[r + g    ][8 * ks + tq];
                af[mi][1] = As[r + 8 + g][8 * ks + tq];
                af[mi][2] = As[r + g    ][8 * ks + tq + 4];
                af[mi][3] = As[r + 8 + g][8 * ks + tq + 4];
            }
#pragma unroll
            for (int nj = 0; nj < 4; ++nj) {
                int c = wn * 32 + 8 * nj;
                bf[nj][0] = Bs[c + g][8 * ks + tq];
                bf[nj][1] = Bs[c + g][8 * ks + tq + 4];
            }
#pragma unroll
            for (int mi = 0; mi < 4; ++mi)
#pragma unroll
                for (int nj = 0; nj < 4; ++nj)
                    mma_tf32(acc[mi][nj], af[mi], bf[nj]);
        }
    }

    // Epilogue: fragment (row g / g+8, cols 2tq, 2tq+1)
#pragma unroll
    for (int mi = 0; mi < 4; ++mi) {
#pragma unroll
        for (int rr = 0; rr < 2; ++rr) {
            int gm = m0 + wm * 64 + 16 * mi + g + 8 * rr;
#pragma unroll
            for (int nj = 0; nj < 4; ++nj) {
                int gn = n0 + wn * 32 + 8 * nj + 2 * tq;
                float v0 = acc[mi][nj][2 * rr], v1 = acc[mi][nj][2 * rr + 1];
                if (mode == 0) {
                    float2 o = { v0 + bias[gn], v1 + bias[gn + 1] };
                    *(float2*)(Cout + (size_t)gm * Dmod + gn) = o;
                } else {
                    int hh = gn >> 6, dd = gn & 63;
                    float2 o = { v0, v1 };
                    if (mode == 1) {
                        int b = gm >> 10, tok = gm & 1023;
                        *(float2*)(g_Q + (((size_t)(b * Hn + hh)) * Ntok + tok) * HDim + dd) = o;
                    } else {
                        int b, seq;
                        if (gm < MROWS) { b = gm >> 10; seq = gm & 1023; }
                        else { int m2 = gm - MROWS; b = m2 >> 10; seq = Ntok + (m2 & 1023); }
                        float* dst = (mode == 2) ? g_K : g_V;
                        *(float2*)(dst + (((size_t)(b * Hn + hh)) * N2 + seq) * HDim + dd) = o;
                    }
                }
            }
        }
    }
}

// ---------------------------------------------------------------------------
// Attention via mma. grid=(16, 96), 128 threads (4 warps); warp w owns q-rows
// 16w..16w+15. Q lives in registers as A-fragments. K/V share one smem buffer.
// ---------------------------------------------------------------------------
#define KSTR 68   // KVs row stride: S-phase B frags conflict-free (4g+t)

__global__ __launch_bounds__(128)
void attn_mma()
{
    __shared__ unsigned KVs[64][KSTR];
    __shared__ unsigned Ps [64][KSTR];

    const int t = threadIdx.x, lane = t & 31, warp = t >> 5;
    const int g = lane >> 2, tq = lane & 3;
    const int q0 = blockIdx.x * 64, bh = blockIdx.y;
    const int b = bh / Hn, h = bh - b * Hn;

    const float* Qg = g_Q + ((size_t)bh * Ntok + q0) * HDim;
    const float* Kg = g_K + (size_t)bh * N2 * HDim;
    const float* Vg = g_V + (size_t)bh * N2 * HDim;

    // Stage Q (scaled) through smem, pull into register A-fragments
    for (int i = t; i < 1024; i += 128) {
        int r = i >> 4, c4 = (i & 15) * 4;
        float4 v = *(const float4*)(Qg + r * HDim + c4);
        uint4 w = { f2tf(v.x * 0.125f), f2tf(v.y * 0.125f),
                    f2tf(v.z * 0.125f), f2tf(v.w * 0.125f) };
        *(uint4*)&KVs[r][c4] = w;
    }
    __syncthreads();

    unsigned qa[8][4];
#pragma unroll
    for (int ks = 0; ks < 8; ++ks) {
        qa[ks][0] = KVs[16 * warp + g    ][8 * ks + tq];
        qa[ks][1] = KVs[16 * warp + 8 + g][8 * ks + tq];
        qa[ks][2] = KVs[16 * warp + g    ][8 * ks + tq + 4];
        qa[ks][3] = KVs[16 * warp + 8 + g][8 * ks + tq + 4];
    }

    float m0 = -1e30f, m1 = -1e30f, l0 = 0.f, l1 = 0.f;
    float O[8][4];
#pragma unroll
    for (int j = 0; j < 8; ++j)
#pragma unroll
        for (int c = 0; c < 4; ++c) O[j][c] = 0.f;

    for (int k0 = 0; k0 < N2; k0 += 64) {
        __syncthreads();                         // Q frags read / prev V reads done
        for (int i = t; i < 1024; i += 128) {
            int r = i >> 4, c4 = (i & 15) * 4;
            float4 v = *(const float4*)(Kg + (size_t)(k0 + r) * HDim + c4);
            uint4 w = { f2tf(v.x), f2tf(v.y), f2tf(v.z), f2tf(v.w) };
            *(uint4*)&KVs[r][c4] = w;
        }
        __syncthreads();

        // S = Q K^T  (per warp: 16 rows x 64 cols)
        float S[8][4];
#pragma unroll
        for (int j = 0; j < 8; ++j)
#pragma unroll
            for (int c = 0; c < 4; ++c) S[j][c] = 0.f;
#pragma unroll
        for (int ks = 0; ks < 8; ++ks) {
#pragma unroll
            for (int j = 0; j < 8; ++j) {
                unsigned bb[2] = { KVs[8 * j + g][8 * ks + tq],
                                   KVs[8 * j + g][8 * ks + tq + 4] };
                mma_tf32(S[j], qa[ks], bb);
            }
        }

        // Online softmax (rows g and g+8; row spread over quad lanes)
        float mt0 = -1e30f, mt1 = -1e30f;
#pragma unroll
        for (int j = 0; j < 8; ++j) {
            mt0 = fmaxf(mt0, fmaxf(S[j][0], S[j][1]));
            mt1 = fmaxf(mt1, fmaxf(S[j][2], S[j][3]));
        }
        mt0 = fmaxf(mt0, __shfl_xor_sync(0xffffffffu, mt0, 1));
        mt0 = fmaxf(mt0, __shfl_xor_sync(0xffffffffu, mt0, 2));
        mt1 = fmaxf(mt1, __shfl_xor_sync(0xffffffffu, mt1, 1));
        mt1 = fmaxf(mt1, __shfl_xor_sync(0xffffffffu, mt1, 2));
        float mn0 = fmaxf(m0, mt0), mn1 = fmaxf(m1, mt1);
        float a0 = __expf(m0 - mn0), a1 = __expf(m1 - mn1);
        float ls0 = 0.f, ls1 = 0.f;
#pragma unroll
        for (int j = 0; j < 8; ++j) {
            S[j][0] = __expf(S[j][0] - mn0);
            S[j][1] = __expf(S[j][1] - mn0);
            S[j][2] = __expf(S[j][2] - mn1);
            S[j][3] = __expf(S[j][3] - mn1);
            ls0 += S[j][0] + S[j][1];
            ls1 += S[j][2] + S[j][3];
        }
        ls0 += __shfl_xor_sync(0xffffffffu, ls0, 1);
        ls0 += __shfl_xor_sync(0xffffffffu, ls0, 2);
        ls1 += __shfl_xor_sync(0xffffffffu, ls1, 1);
        ls1 += __shfl_xor_sync(0xffffffffu, ls1, 2);
        l0 = l0 * a0 + ls0;  l1 = l1 * a1 + ls1;
        m0 = mn0;  m1 = mn1;
#pragma unroll
        for (int j = 0; j < 8; ++j) {
            O[j][0] *= a0; O[j][1] *= a0; O[j][2] *= a1; O[j][3] *= a1;
        }

        // P -> smem (tf32 bits)
#pragma unroll
        for (int j = 0; j < 8; ++j) {
            Ps[16 * warp + g    ][8 * j + 2 * tq    ] = f2tf(S[j][0]);
            Ps[16 * warp + g    ][8 * j + 2 * tq + 1] = f2tf(S[j][1]);
            Ps[16 * warp + 8 + g][8 * j + 2 * tq    ] = f2tf(S[j][2]);
            Ps[16 * warp + 8 + g][8 * j + 2 * tq + 1] = f2tf(S[j][3]);
        }

        __syncthreads();                         // all warps done reading K
        for (int i = t; i < 1024; i += 128) {
            int r = i >> 4, c4 = (i & 15) * 4;
            float4 v = *(const float4*)(Vg + (size_t)(k0 + r) * HDim + c4);
            uint4 w = { f2tf(v.x), f2tf(v.y), f2tf(v.z), f2tf(v.w) };
            *(uint4*)&KVs[r][c4] = w;
        }
        __syncthreads();

        // O += P V
#pragma unroll
        for (int ks = 0; ks < 8; ++ks) {
            unsigned pa[4] = { Ps[16 * warp + g    ][8 * ks + tq],
                               Ps[16 * warp + 8 + g][8 * ks + tq],
                               Ps[16 * warp + g    ][8 * ks + tq + 4],
                               Ps[16 * warp + 8 + g][8 * ks + tq + 4] };
#pragma unroll
            for (int j = 0; j < 8; ++j) {
                unsigned bb[2] = { KVs[8 * ks + tq    ][8 * j + g],
                                   KVs[8 * ks + tq + 4][8 * j + g] };
                mma_tf32(O[j], pa, bb);
            }
        }
    }

    float i0 = 1.f / l0, i1 = 1.f / l1;
    float* d0 = g_ctx + ((size_t)(b * Ntok + q0 + 16 * warp + g    )) * Dmod + h * HDim;
    float* d1 = g_ctx + ((size_t)(b * Ntok + q0 + 16 * warp + 8 + g)) * Dmod + h * HDim;
#pragma unroll
    for (int j = 0; j < 8; ++j) {
        float2 o0 = { O[j][0] * i0, O[j][1] * i0 };
        float2 o1 = { O[j][2] * i1, O[j][3] * i1 };
        *(float2*)(d0 + 8 * j + 2 * tq) = o0;
        *(float2*)(d1 + 8 * j + 2 * tq) = o1;
    }
}

// ---------------------------------------------------------------------------
extern "C" void kernel_launch(void* const* d_in, const int* in_sizes, int n_in,
                              void* d_out, int out_size)
{
    const float* x1 = (const float*)d_in[0];
    const float* x2 = (const float*)d_in[1];
    const float* Wq = (const float*)d_in[2];
    const float* Wk = (const float*)d_in[3];
    const float* Wv = (const float*)d_in[4];
    const float* Wo = (const float*)d_in[5];
    const float* bo = (const float*)d_in[6];
    float* out = (float*)d_out;

    dim3 blk(256);
    dim3 gq (Dmod / GBN, MROWS / GBM);         // (6, 64)
    dim3 gkv(Dmod / GBN, 2 * MROWS / GBM);     // (6, 128)

    gemm_tf32<<<gq,  blk>>>(x1, nullptr, Wq, nullptr, nullptr, 1);   // Q
    gemm_tf32<<<gkv, blk>>>(x1, x2,      Wk, nullptr, nullptr, 2);   // K (concat)
    gemm_tf32<<<gkv, blk>>>(x1, x2,      Wv, nullptr, nullptr, 3);   // V (concat)
    attn_mma<<<dim3(Ntok / 64, Bsz * Hn), 128>>>();                  // ctx
    gemm_tf32<<<gq,  blk>>>(nullptr, nullptr, Wo, bo, out, 0);       // out proj
}

// round 4
// speedup vs baseline: 6.4604x; 1.3982x over previous
#include <cuda_runtime.h>
#include <cuda_fp16.h>

// ---------------------------------------------------------------------------
// PairWiseCrossAttention (B=8, N=1024, D=768, H=12, HD=64) — Round 4
// (Round-3 kernel resubmitted after infra flake):
// fp16 mma.m16n8k16 everywhere, ldmatrix fragment loads, register-resident P
// (FA-2 C->A layout trick), cp.async double-buffered K/V, fp16 scratch.
// ---------------------------------------------------------------------------

#define Bsz   8
#define Ntok  1024
#define Dmod  768
#define Hn    12
#define HDim  64
#define N2    2048
#define MROWS 8192

// fp16 scratch
__device__ __half g_Q  [(size_t)Bsz * Hn * Ntok * HDim];
__device__ __half g_K  [(size_t)Bsz * Hn * N2   * HDim];
__device__ __half g_V  [(size_t)Bsz * Hn * N2   * HDim];
__device__ __half g_ctx[(size_t)Bsz * Ntok * Dmod];

#define QSC 0.1803368801111204f   // 0.125 * log2(e): softmax done in exp2 domain

__device__ __forceinline__ unsigned smaddr(const void* p) {
    return (unsigned)__cvta_generic_to_shared(p);
}
__device__ __forceinline__ void ldsm4(unsigned* r, const void* p) {
    asm volatile("ldmatrix.sync.aligned.m8n8.x4.shared.b16 {%0,%1,%2,%3},[%4];"
        : "=r"(r[0]), "=r"(r[1]), "=r"(r[2]), "=r"(r[3]) : "r"(smaddr(p)));
}
__device__ __forceinline__ void ldsm4t(unsigned* r, const void* p) {
    asm volatile("ldmatrix.sync.aligned.m8n8.x4.trans.shared.b16 {%0,%1,%2,%3},[%4];"
        : "=r"(r[0]), "=r"(r[1]), "=r"(r[2]), "=r"(r[3]) : "r"(smaddr(p)));
}
__device__ __forceinline__ void mma16816(float* c, const unsigned* a, const unsigned* b) {
    asm volatile("mma.sync.aligned.m16n8k16.row.col.f32.f16.f16.f32 "
        "{%0,%1,%2,%3},{%4,%5,%6,%7},{%8,%9},{%0,%1,%2,%3};"
        : "+f"(c[0]), "+f"(c[1]), "+f"(c[2]), "+f"(c[3])
        : "r"(a[0]), "r"(a[1]), "r"(a[2]), "r"(a[3]), "r"(b[0]), "r"(b[1]));
}
__device__ __forceinline__ unsigned h2pack(float x, float y) {
    __half2 h = __floats2half2_rn(x, y);
    return *(unsigned*)&h;
}
__device__ __forceinline__ void cpasync16(void* dst, const void* src) {
    asm volatile("cp.async.cg.shared.global [%0],[%1],16;" :: "r"(smaddr(dst)), "l"(src));
}

// ---------------------------------------------------------------------------
// GEMM: C = A @ W^T (+bias). 128x128 block, BK=32, 8 warps (64x32 warp tile).
// mode 0: A=g_ctx (fp16) -> Cout fp32 + bias
// mode 1: A=x1           -> g_Q heads (scaled by QSC)
// mode 2/3: A=[x1;x2]    -> g_K / g_V heads
// ---------------------------------------------------------------------------
#define GBM 128
#define GBN 128
#define GBK 32
#define AST 40    // smem stride (halves): 80B rows, ldmatrix conflict-free

__global__ __launch_bounds__(256)
void gemm_h(const float* __restrict__ A0, const float* __restrict__ A1,
            const float* __restrict__ W,  const float* __restrict__ bias,
            float* __restrict__ Cout, int mode)
{
    __shared__ __half As[GBM][AST];
    __shared__ __half Bs[GBN][AST];

    const int tid  = threadIdx.x;
    const int lane = tid & 31, warp = tid >> 5;
    const int g = lane >> 2, tq = lane & 3;
    const int wm = warp >> 2, wn = warp & 3;
    const int m0 = blockIdx.y * GBM, n0 = blockIdx.x * GBN;

    const float* A = A0;
    int mrow = m0;
    if ((mode == 2 || mode == 3) && m0 >= MROWS) { A = A1; mrow = m0 - MROWS; }
    const __half* Ah = g_ctx;   // mode 0 source

    const int r  = tid & 127;
    const int kq = (tid >> 7) * 16;      // 0 or 16 (halves / floats within BK)

    float acc[4][4][4];
#pragma unroll
    for (int i = 0; i < 4; ++i)
#pragma unroll
        for (int j = 0; j < 4; ++j)
#pragma unroll
            for (int c = 0; c < 4; ++c) acc[i][j][c] = 0.f;

    float4 pa[4], pb[4];
    uint4  pah[2];
    if (mode == 0) {
        pah[0] = *(const uint4*)(Ah + (size_t)(m0 + r) * Dmod + kq);
        pah[1] = *(const uint4*)(Ah + (size_t)(m0 + r) * Dmod + kq + 8);
    } else {
#pragma unroll
        for (int u = 0; u < 4; ++u)
            pa[u] = *(const float4*)(A + (size_t)(mrow + r) * Dmod + kq + 4 * u);
    }
#pragma unroll
    for (int u = 0; u < 4; ++u)
        pb[u] = *(const float4*)(W + (size_t)(n0 + r) * Dmod + kq + 4 * u);

    for (int k0 = 0; k0 < Dmod; k0 += GBK) {
        __syncthreads();
        if (mode == 0) {
            *(uint4*)&As[r][kq    ] = pah[0];
            *(uint4*)&As[r][kq + 8] = pah[1];
        } else {
            uint4 wa0 = { h2pack(pa[0].x, pa[0].y), h2pack(pa[0].z, pa[0].w),
                          h2pack(pa[1].x, pa[1].y), h2pack(pa[1].z, pa[1].w) };
            uint4 wa1 = { h2pack(pa[2].x, pa[2].y), h2pack(pa[2].z, pa[2].w),
                          h2pack(pa[3].x, pa[3].y), h2pack(pa[3].z, pa[3].w) };
            *(uint4*)&As[r][kq    ] = wa0;
            *(uint4*)&As[r][kq + 8] = wa1;
        }
        {
            uint4 wb0 = { h2pack(pb[0].x, pb[0].y), h2pack(pb[0].z, pb[0].w),
                          h2pack(pb[1].x, pb[1].y), h2pack(pb[1].z, pb[1].w) };
            uint4 wb1 = { h2pack(pb[2].x, pb[2].y), h2pack(pb[2].z, pb[2].w),
                          h2pack(pb[3].x, pb[3].y), h2pack(pb[3].z, pb[3].w) };
            *(uint4*)&Bs[r][kq    ] = wb0;
            *(uint4*)&Bs[r][kq + 8] = wb1;
        }
        __syncthreads();

        if (k0 + GBK < Dmod) {
            if (mode == 0) {
                pah[0] = *(const uint4*)(Ah + (size_t)(m0 + r) * Dmod + k0 + GBK + kq);
                pah[1] = *(const uint4*)(Ah + (size_t)(m0 + r) * Dmod + k0 + GBK + kq + 8);
            } else {
#pragma unroll
                for (int u = 0; u < 4; ++u)
                    pa[u] = *(const float4*)(A + (size_t)(mrow + r) * Dmod + k0 + GBK + kq + 4 * u);
            }
#pragma unroll
            for (int u = 0; u < 4; ++u)
                pb[u] = *(const float4*)(W + (size_t)(n0 + r) * Dmod + k0 + GBK + kq + 4 * u);
        }

#pragma unroll
        for (int ks = 0; ks < 2; ++ks) {
            unsigned af[4][4], bf[4][2];
#pragma unroll
            for (int mi = 0; mi < 4; ++mi)
                ldsm4(af[mi], &As[wm * 64 + mi * 16 + (lane & 15)][ks * 16 + (lane >> 4) * 8]);
#pragma unroll
            for (int pr = 0; pr < 2; ++pr) {
                unsigned t4[4];
                ldsm4(t4, &Bs[wn * 32 + pr * 16 + (lane & 7) + ((lane >> 4) << 3)]
                           [ks * 16 + ((lane >> 3) & 1) * 8]);
                bf[2 * pr    ][0] = t4[0]; bf[2 * pr    ][1] = t4[1];
                bf[2 * pr + 1][0] = t4[2]; bf[2 * pr + 1][1] = t4[3];
            }
#pragma unroll
            for (int mi = 0; mi < 4; ++mi)
#pragma unroll
                for (int nj = 0; nj < 4; ++nj)
                    mma16816(acc[mi][nj], af[mi], bf[nj]);
        }
    }

    // Epilogue
#pragma unroll
    for (int mi = 0; mi < 4; ++mi) {
#pragma unroll
        for (int rr = 0; rr < 2; ++rr) {
            int gm = m0 + wm * 64 + 16 * mi + g + 8 * rr;
#pragma unroll
            for (int nj = 0; nj < 4; ++nj) {
                int gn = n0 + wn * 32 + 8 * nj + 2 * tq;
                float v0 = acc[mi][nj][2 * rr], v1 = acc[mi][nj][2 * rr + 1];
                if (mode == 0) {
                    float2 o = { v0 + bias[gn], v1 + bias[gn + 1] };
                    *(float2*)(Cout + (size_t)gm * Dmod + gn) = o;
                } else {
                    int hh = gn >> 6, dd = gn & 63;
                    if (mode == 1) {
                        int b = gm >> 10, tok = gm & 1023;
                        *(__half2*)(g_Q + (((size_t)(b * Hn + hh)) * Ntok + tok) * HDim + dd)
                            = __floats2half2_rn(v0 * QSC, v1 * QSC);
                    } else {
                        int b, seq;
                        if (gm < MROWS) { b = gm >> 10; seq = gm & 1023; }
                        else { int m2 = gm - MROWS; b = m2 >> 10; seq = Ntok + (m2 & 1023); }
                        __half* dst = (mode == 2) ? g_K : g_V;
                        *(__half2*)(dst + (((size_t)(b * Hn + hh)) * N2 + seq) * HDim + dd)
                            = __floats2half2_rn(v0, v1);
                    }
                }
            }
        }
    }
}

// ---------------------------------------------------------------------------
// Attention. grid=(16, 96), 128 threads; warp w owns q rows 16w..16w+15.
// Q in register A-frags; K/V cp.async double-buffered; P stays in registers
// (C-frag of S == A-frag of PV after half2 packing). Softmax in exp2 domain.
// ---------------------------------------------------------------------------
#define KST 72   // 144B row stride: conflict-free ldmatrix groups

__global__ __launch_bounds__(128)
void attn_h()
{
    __shared__ __half Qs[64][KST];
    __shared__ __half Ks[2][64][KST];
    __shared__ __half Vs[2][64][KST];

    const int t = threadIdx.x, lane = t & 31, warp = t >> 5;
    const int g = lane >> 2, tq = lane & 3;
    const int q0 = blockIdx.x * 64, bh = blockIdx.y;
    const int b = bh / Hn, h = bh - b * Hn;

    const __half* Qg = g_Q + ((size_t)bh * Ntok + q0) * HDim;
    const __half* Kg = g_K + (size_t)bh * N2 * HDim;
    const __half* Vg = g_V + (size_t)bh * N2 * HDim;

    auto issue = [&](int buf, int k0) {
        for (int i = t; i < 512; i += 128) {
            int r = i >> 3, c = (i & 7) * 8;
            cpasync16(&Ks[buf][r][c], Kg + (size_t)(k0 + r) * HDim + c);
            cpasync16(&Vs[buf][r][c], Vg + (size_t)(k0 + r) * HDim + c);
        }
        asm volatile("cp.async.commit_group;");
    };
    issue(0, 0);

    for (int i = t; i < 512; i += 128) {
        int r = i >> 3, c = (i & 7) * 8;
        *(uint4*)&Qs[r][c] = *(const uint4*)(Qg + (size_t)r * HDim + c);
    }
    __syncthreads();

    unsigned qa[4][4];
#pragma unroll
    for (int ks = 0; ks < 4; ++ks)
        ldsm4(qa[ks], &Qs[16 * warp + (lane & 15)][ks * 16 + (lane >> 4) * 8]);

    float m0 = -1e30f, m1 = -1e30f, l0 = 0.f, l1 = 0.f;
    float O[8][4];
#pragma unroll
    for (int j = 0; j < 8; ++j)
#pragma unroll
        for (int c = 0; c < 4; ++c) O[j][c] = 0.f;

    for (int it = 0; it < 32; ++it) {
        const int buf = it & 1;
        if (it < 31) {
            issue(buf ^ 1, (it + 1) * 64);
            asm volatile("cp.async.wait_group 1;");
        } else {
            asm volatile("cp.async.wait_group 0;");
        }
        __syncthreads();

        // S = Q K^T  (16 q-rows x 64 keys per warp), log2-domain scores
        float S[8][4];
#pragma unroll
        for (int j = 0; j < 8; ++j)
#pragma unroll
            for (int c = 0; c < 4; ++c) S[j][c] = 0.f;
#pragma unroll
        for (int ks = 0; ks < 4; ++ks) {
#pragma unroll
            for (int pr = 0; pr < 4; ++pr) {
                unsigned t4[4];
                ldsm4(t4, &Ks[buf][pr * 16 + (lane & 7) + ((lane >> 4) << 3)]
                           [ks * 16 + ((lane >> 3) & 1) * 8]);
                mma16816(S[2 * pr    ], qa[ks], t4);
                mma16816(S[2 * pr + 1], qa[ks], t4 + 2);
            }
        }

        // Online softmax (exp2 domain); rows g (c0,c1) and g+8 (c2,c3)
        float mt0 = -1e30f, mt1 = -1e30f;
#pragma unroll
        for (int j = 0; j < 8; ++j) {
            mt0 = fmaxf(mt0, fmaxf(S[j][0], S[j][1]));
            mt1 = fmaxf(mt1, fmaxf(S[j][2], S[j][3]));
        }
        mt0 = fmaxf(mt0, __shfl_xor_sync(0xffffffffu, mt0, 1));
        mt0 = fmaxf(mt0, __shfl_xor_sync(0xffffffffu, mt0, 2));
        mt1 = fmaxf(mt1, __shfl_xor_sync(0xffffffffu, mt1, 1));
        mt1 = fmaxf(mt1, __shfl_xor_sync(0xffffffffu, mt1, 2));
        float mn0 = fmaxf(m0, mt0), mn1 = fmaxf(m1, mt1);
        float a0 = exp2f(m0 - mn0), a1 = exp2f(m1 - mn1);
        float ls0 = 0.f, ls1 = 0.f;
#pragma unroll
        for (int j = 0; j < 8; ++j) {
            S[j][0] = exp2f(S[j][0] - mn0);
            S[j][1] = exp2f(S[j][1] - mn0);
            S[j][2] = exp2f(S[j][2] - mn1);
            S[j][3] = exp2f(S[j][3] - mn1);
            ls0 += S[j][0] + S[j][1];
            ls1 += S[j][2] + S[j][3];
        }
        ls0 += __shfl_xor_sync(0xffffffffu, ls0, 1);
        ls0 += __shfl_xor_sync(0xffffffffu, ls0, 2);
        ls1 += __shfl_xor_sync(0xffffffffu, ls1, 1);
        ls1 += __shfl_xor_sync(0xffffffffu, ls1, 2);
        l0 = l0 * a0 + ls0;  l1 = l1 * a1 + ls1;
        m0 = mn0;  m1 = mn1;
#pragma unroll
        for (int j = 0; j < 8; ++j) {
            O[j][0] *= a0; O[j][1] *= a0; O[j][2] *= a1; O[j][3] *= a1;
        }

        // P packed to half A-frags in registers (C->A layout identity)
        unsigned pf[4][4];
#pragma unroll
        for (int kc = 0; kc < 4; ++kc) {
            int j0 = 2 * kc, j1 = 2 * kc + 1;
            pf[kc][0] = h2pack(S[j0][0], S[j0][1]);
            pf[kc][1] = h2pack(S[j0][2], S[j0][3]);
            pf[kc][2] = h2pack(S[j1][0], S[j1][1]);
            pf[kc][3] = h2pack(S[j1][2], S[j1][3]);
        }

        // O += P V
#pragma unroll
        for (int kc = 0; kc < 4; ++kc) {
#pragma unroll
            for (int pr = 0; pr < 4; ++pr) {
                unsigned t4[4];
                ldsm4t(t4, &Vs[buf][kc * 16 + (lane & 7) + ((lane >> 3) & 1) * 8]
                            [8 * (2 * pr + (lane >> 4))]);
                mma16816(O[2 * pr    ], pf[kc], t4);
                mma16816(O[2 * pr + 1], pf[kc], t4 + 2);
            }
        }
        __syncthreads();
    }

    float i0 = 1.f / l0, i1 = 1.f / l1;
    __half* d0 = g_ctx + ((size_t)(b * Ntok + q0 + 16 * warp + g    )) * Dmod + h * HDim;
    __half* d1 = g_ctx + ((size_t)(b * Ntok + q0 + 16 * warp + 8 + g)) * Dmod + h * HDim;
#pragma unroll
    for (int nj = 0; nj < 8; ++nj) {
        *(__half2*)(d0 + 8 * nj + 2 * tq) = __floats2half2_rn(O[nj][0] * i0, O[nj][1] * i0);
        *(__half2*)(d1 + 8 * nj + 2 * tq) = __floats2half2_rn(O[nj][2] * i1, O[nj][3] * i1);
    }
}

// ---------------------------------------------------------------------------
extern "C" void kernel_launch(void* const* d_in, const int* in_sizes, int n_in,
                              void* d_out, int out_size)
{
    const float* x1 = (const float*)d_in[0];
    const float* x2 = (const float*)d_in[1];
    const float* Wq = (const float*)d_in[2];
    const float* Wk = (const float*)d_in[3];
    const float* Wv = (const float*)d_in[4];
    const float* Wo = (const float*)d_in[5];
    const float* bo = (const float*)d_in[6];
    float* out = (float*)d_out;

    dim3 blk(256);
    dim3 gq (Dmod / GBN, MROWS / GBM);         // (6, 64)
    dim3 gkv(Dmod / GBN, 2 * MROWS / GBM);     // (6, 128)

    gemm_h<<<gq,  blk>>>(x1, nullptr, Wq, nullptr, nullptr, 1);   // Q (scaled)
    gemm_h<<<gkv, blk>>>(x1, x2,      Wk, nullptr, nullptr, 2);   // K (concat)
    gemm_h<<<gkv, blk>>>(x1, x2,      Wv, nullptr, nullptr, 3);   // V (concat)
    attn_h<<<dim3(Ntok / 64, Bsz * Hn), 128>>>();                 // ctx
    gemm_h<<<gq,  blk>>>(nullptr, nullptr, Wo, bo, out, 0);       // out proj
}

// round 10
// speedup vs baseline: 6.4621x; 1.0003x over previous
#include <cuda_runtime.h>
#include <cuda_fp16.h>

// ---------------------------------------------------------------------------
// PairWiseCrossAttention (B=8, N=1024, D=768, H=12, HD=64) — Round 10:
// Exactly the Round-4 kernel (848us, passed) with ONE change: the GEMM
// mainloop is smem-double-buffered with a single __syncthreads per BK tile,
// STS issued before mma so stores drain under tensor work.
// Globals identical to R4 (75.5MB). No conv pass, no d_out scratch.
// ---------------------------------------------------------------------------

#define Bsz   8
#define Ntok  1024
#define Dmod  768
#define Hn    12
#define HDim  64
#define N2    2048
#define MROWS 8192

// fp16 scratch — identical set/sizes to Round 4
__device__ __half g_Q  [(size_t)Bsz * Hn * Ntok * HDim];
__device__ __half g_K  [(size_t)Bsz * Hn * N2   * HDim];
__device__ __half g_V  [(size_t)Bsz * Hn * N2   * HDim];
__device__ __half g_ctx[(size_t)Bsz * Ntok * Dmod];

#define QSC 0.1803368801111204f   // 0.125 * log2(e): softmax in exp2 domain

__device__ __forceinline__ unsigned smaddr(const void* p) {
    return (unsigned)__cvta_generic_to_shared(p);
}
__device__ __forceinline__ void ldsm4(unsigned* r, const void* p) {
    asm volatile("ldmatrix.sync.aligned.m8n8.x4.shared.b16 {%0,%1,%2,%3},[%4];"
        : "=r"(r[0]), "=r"(r[1]), "=r"(r[2]), "=r"(r[3]) : "r"(smaddr(p)));
}
__device__ __forceinline__ void ldsm4t(unsigned* r, const void* p) {
    asm volatile("ldmatrix.sync.aligned.m8n8.x4.trans.shared.b16 {%0,%1,%2,%3},[%4];"
        : "=r"(r[0]), "=r"(r[1]), "=r"(r[2]), "=r"(r[3]) : "r"(smaddr(p)));
}
__device__ __forceinline__ void mma16816(float* c, const unsigned* a, const unsigned* b) {
    asm volatile("mma.sync.aligned.m16n8k16.row.col.f32.f16.f16.f32 "
        "{%0,%1,%2,%3},{%4,%5,%6,%7},{%8,%9},{%0,%1,%2,%3};"
        : "+f"(c[0]), "+f"(c[1]), "+f"(c[2]), "+f"(c[3])
        : "r"(a[0]), "r"(a[1]), "r"(a[2]), "r"(a[3]), "r"(b[0]), "r"(b[1]));
}
__device__ __forceinline__ unsigned h2pack(float x, float y) {
    __half2 h = __floats2half2_rn(x, y);
    return *(unsigned*)&h;
}
__device__ __forceinline__ void cpasync16(void* dst, const void* src) {
    asm volatile("cp.async.cg.shared.global [%0],[%1],16;" :: "r"(smaddr(dst)), "l"(src));
}

// ---------------------------------------------------------------------------
// GEMM: C = A @ W^T (+bias). 128x128 block, BK=32, 8 warps (64x32 warp tile).
// Double-buffered smem, ONE barrier per tile.
// mode 0: A=g_ctx (fp16) -> Cout fp32 + bias
// mode 1: A=x1           -> g_Q heads (scaled by QSC)
// mode 2/3: A=[x1;x2]    -> g_K / g_V heads
// ---------------------------------------------------------------------------
#define GBM 128
#define GBN 128
#define GBK 32
#define AST 40    // smem stride (halves): 80B rows, ldmatrix conflict-free (R4-proven)
#define NKIT 24   // 768/32

#define LOAD_REGS(kbase) do {                                                    \
    if (mode == 0) {                                                             \
        pah[0] = *(const uint4*)(Ah + (size_t)(m0 + r) * Dmod + (kbase) + kq);   \
        pah[1] = *(const uint4*)(Ah + (size_t)(m0 + r) * Dmod + (kbase) + kq + 8);\
    } else {                                                                     \
        pa[0] = *(const float4*)(A + (size_t)(mrow + r) * Dmod + (kbase) + kq);  \
        pa[1] = *(const float4*)(A + (size_t)(mrow + r) * Dmod + (kbase) + kq + 4);\
        pa[2] = *(const float4*)(A + (size_t)(mrow + r) * Dmod + (kbase) + kq + 8);\
        pa[3] = *(const float4*)(A + (size_t)(mrow + r) * Dmod + (kbase) + kq + 12);\
    }                                                                            \
    pb[0] = *(const float4*)(W + (size_t)(n0 + r) * Dmod + (kbase) + kq);        \
    pb[1] = *(const float4*)(W + (size_t)(n0 + r) * Dmod + (kbase) + kq + 4);    \
    pb[2] = *(const float4*)(W + (size_t)(n0 + r) * Dmod + (kbase) + kq + 8);    \
    pb[3] = *(const float4*)(W + (size_t)(n0 + r) * Dmod + (kbase) + kq + 12);   \
} while (0)

#define STS_STAGE(st) do {                                                       \
    if (mode == 0) {                                                             \
        *(uint4*)&As[(st)][r][kq    ] = pah[0];                                  \
        *(uint4*)&As[(st)][r][kq + 8] = pah[1];                                  \
    } else {                                                                     \
        uint4 wa0 = { h2pack(pa[0].x, pa[0].y), h2pack(pa[0].z, pa[0].w),        \
                      h2pack(pa[1].x, pa[1].y), h2pack(pa[1].z, pa[1].w) };      \
        uint4 wa1 = { h2pack(pa[2].x, pa[2].y), h2pack(pa[2].z, pa[2].w),        \
                      h2pack(pa[3].x, pa[3].y), h2pack(pa[3].z, pa[3].w) };      \
        *(uint4*)&As[(st)][r][kq    ] = wa0;                                     \
        *(uint4*)&As[(st)][r][kq + 8] = wa1;                                     \
    }                                                                            \
    {                                                                            \
        uint4 wb0 = { h2pack(pb[0].x, pb[0].y), h2pack(pb[0].z, pb[0].w),        \
                      h2pack(pb[1].x, pb[1].y), h2pack(pb[1].z, pb[1].w) };      \
        uint4 wb1 = { h2pack(pb[2].x, pb[2].y), h2pack(pb[2].z, pb[2].w),        \
                      h2pack(pb[3].x, pb[3].y), h2pack(pb[3].z, pb[3].w) };      \
        *(uint4*)&Bs[(st)][r][kq    ] = wb0;                                     \
        *(uint4*)&Bs[(st)][r][kq + 8] = wb1;                                     \
    }                                                                            \
} while (0)

__global__ __launch_bounds__(256)
void gemm_h(const float* __restrict__ A0, const float* __restrict__ A1,
            const float* __restrict__ W,  const float* __restrict__ bias,
            float* __restrict__ Cout, int mode)
{
    __shared__ __half As[2][GBM][AST];
    __shared__ __half Bs[2][GBN][AST];

    const int tid  = threadIdx.x;
    const int lane = tid & 31, warp = tid >> 5;
    const int g = lane >> 2, tq = lane & 3;
    const int wm = warp >> 2, wn = warp & 3;
    const int m0 = blockIdx.y * GBM, n0 = blockIdx.x * GBN;

    const float* A = A0;
    int mrow = m0;
    if ((mode == 2 || mode == 3) && m0 >= MROWS) { A = A1; mrow = m0 - MROWS; }
    const __half* Ah = g_ctx;   // mode 0 source

    const int r  = tid & 127;
    const int kq = (tid >> 7) * 16;      // 0 or 16 (halves / floats within BK)

    float acc[4][4][4];
#pragma unroll
    for (int i = 0; i < 4; ++i)
#pragma unroll
        for (int j = 0; j < 4; ++j)
#pragma unroll
            for (int c = 0; c < 4; ++c) acc[i][j][c] = 0.f;

    float4 pa[4], pb[4];
    uint4  pah[2];

    // Prologue: tile 0 -> stage 0; prefetch tile 1 into regs.
    LOAD_REGS(0);
    STS_STAGE(0);
    __syncthreads();
    LOAD_REGS(GBK);

    // Mainloop: tile it lives in stage it&1. One barrier per iteration.
    // STS(it+1) is safe before the barrier: stage (it+1)&1 was last read at
    // it-1, and it-1's trailing barrier ordered that read before this write.
    for (int it = 0; it < NKIT; ++it) {
        const int cur = it & 1;
        if (it + 1 < NKIT) STS_STAGE(cur ^ 1);          // store tile it+1
        if (it + 2 < NKIT) LOAD_REGS((it + 2) * GBK);   // prefetch tile it+2

#pragma unroll
        for (int ks = 0; ks < 2; ++ks) {
            unsigned af[4][4], bf[4][2];
#pragma unroll
            for (int mi = 0; mi < 4; ++mi)
                ldsm4(af[mi], &As[cur][wm * 64 + mi * 16 + (lane & 15)][ks * 16 + (lane >> 4) * 8]);
#pragma unroll
            for (int pr = 0; pr < 2; ++pr) {
                unsigned t4[4];
                ldsm4(t4, &Bs[cur][wn * 32 + pr * 16 + (lane & 7) + ((lane >> 4) << 3)]
                           [ks * 16 + ((lane >> 3) & 1) * 8]);
                bf[2 * pr    ][0] = t4[0]; bf[2 * pr    ][1] = t4[1];
                bf[2 * pr + 1][0] = t4[2]; bf[2 * pr + 1][1] = t4[3];
            }
#pragma unroll
            for (int mi = 0; mi < 4; ++mi)
#pragma unroll
                for (int nj = 0; nj < 4; ++nj)
                    mma16816(acc[mi][nj], af[mi], bf[nj]);
        }
        __syncthreads();
    }

    // Epilogue — identical to Round 4
#pragma unroll
    for (int mi = 0; mi < 4; ++mi) {
#pragma unroll
        for (int rr = 0; rr < 2; ++rr) {
            int gm = m0 + wm * 64 + 16 * mi + g + 8 * rr;
#pragma unroll
            for (int nj = 0; nj < 4; ++nj) {
                int gn = n0 + wn * 32 + 8 * nj + 2 * tq;
                float v0 = acc[mi][nj][2 * rr], v1 = acc[mi][nj][2 * rr + 1];
                if (mode == 0) {
                    float2 o = { v0 + bias[gn], v1 + bias[gn + 1] };
                    *(float2*)(Cout + (size_t)gm * Dmod + gn) = o;
                } else {
                    int hh = gn >> 6, dd = gn & 63;
                    if (mode == 1) {
                        int b = gm >> 10, tok = gm & 1023;
                        *(__half2*)(g_Q + (((size_t)(b * Hn + hh)) * Ntok + tok) * HDim + dd)
                            = __floats2half2_rn(v0 * QSC, v1 * QSC);
                    } else {
                        int b, seq;
                        if (gm < MROWS) { b = gm >> 10; seq = gm & 1023; }
                        else { int m2 = gm - MROWS; b = m2 >> 10; seq = Ntok + (m2 & 1023); }
                        __half* dst = (mode == 2) ? g_K : g_V;
                        *(__half2*)(dst + (((size_t)(b * Hn + hh)) * N2 + seq) * HDim + dd)
                            = __floats2half2_rn(v0, v1);
                    }
                }
            }
        }
    }
}

// ---------------------------------------------------------------------------
// Attention — byte-identical to Round 4 (measured 207.8us).
// ---------------------------------------------------------------------------
#define KST 72

__global__ __launch_bounds__(128)
void attn_h()
{
    __shared__ __half Qs[64][KST];
    __shared__ __half Ks[2][64][KST];
    __shared__ __half Vs[2][64][KST];

    const int t = threadIdx.x, lane = t & 31, warp = t >> 5;
    const int g = lane >> 2, tq = lane & 3;
    const int q0 = blockIdx.x * 64, bh = blockIdx.y;
    const int b = bh / Hn, h = bh - b * Hn;

    const __half* Qg = g_Q + ((size_t)bh * Ntok + q0) * HDim;
    const __half* Kg = g_K + (size_t)bh * N2 * HDim;
    const __half* Vg = g_V + (size_t)bh * N2 * HDim;

    auto issue = [&](int buf, int k0) {
        for (int i = t; i < 512; i += 128) {
            int r = i >> 3, c = (i & 7) * 8;
            cpasync16(&Ks[buf][r][c], Kg + (size_t)(k0 + r) * HDim + c);
            cpasync16(&Vs[buf][r][c], Vg + (size_t)(k0 + r) * HDim + c);
        }
        asm volatile("cp.async.commit_group;");
    };
    issue(0, 0);

    for (int i = t; i < 512; i += 128) {
        int r = i >> 3, c = (i & 7) * 8;
        *(uint4*)&Qs[r][c] = *(const uint4*)(Qg + (size_t)r * HDim + c);
    }
    __syncthreads();

    unsigned qa[4][4];
#pragma unroll
    for (int ks = 0; ks < 4; ++ks)
        ldsm4(qa[ks], &Qs[16 * warp + (lane & 15)][ks * 16 + (lane >> 4) * 8]);

    float m0 = -1e30f, m1 = -1e30f, l0 = 0.f, l1 = 0.f;
    float O[8][4];
#pragma unroll
    for (int j = 0; j < 8; ++j)
#pragma unroll
        for (int c = 0; c < 4; ++c) O[j][c] = 0.f;

    for (int it = 0; it < 32; ++it) {
        const int buf = it & 1;
        if (it < 31) {
            issue(buf ^ 1, (it + 1) * 64);
            asm volatile("cp.async.wait_group 1;");
        } else {
            asm volatile("cp.async.wait_group 0;");
        }
        __syncthreads();

        float S[8][4];
#pragma unroll
        for (int j = 0; j < 8; ++j)
#pragma unroll
            for (int c = 0; c < 4; ++c) S[j][c] = 0.f;
#pragma unroll
        for (int ks = 0; ks < 4; ++ks) {
#pragma unroll
            for (int pr = 0; pr < 4; ++pr) {
                unsigned t4[4];
                ldsm4(t4, &Ks[buf][pr * 16 + (lane & 7) + ((lane >> 4) << 3)]
                           [ks * 16 + ((lane >> 3) & 1) * 8]);
                mma16816(S[2 * pr    ], qa[ks], t4);
                mma16816(S[2 * pr + 1], qa[ks], t4 + 2);
            }
        }

        float mt0 = -1e30f, mt1 = -1e30f;
#pragma unroll
        for (int j = 0; j < 8; ++j) {
            mt0 = fmaxf(mt0, fmaxf(S[j][0], S[j][1]));
            mt1 = fmaxf(mt1, fmaxf(S[j][2], S[j][3]));
        }
        mt0 = fmaxf(mt0, __shfl_xor_sync(0xffffffffu, mt0, 1));
        mt0 = fmaxf(mt0, __shfl_xor_sync(0xffffffffu, mt0, 2));
        mt1 = fmaxf(mt1, __shfl_xor_sync(0xffffffffu, mt1, 1));
        mt1 = fmaxf(mt1, __shfl_xor_sync(0xffffffffu, mt1, 2));
        float mn0 = fmaxf(m0, mt0), mn1 = fmaxf(m1, mt1);
        float a0 = exp2f(m0 - mn0), a1 = exp2f(m1 - mn1);
        float ls0 = 0.f, ls1 = 0.f;
#pragma unroll
        for (int j = 0; j < 8; ++j) {
            S[j][0] = exp2f(S[j][0] - mn0);
            S[j][1] = exp2f(S[j][1] - mn0);
            S[j][2] = exp2f(S[j][2] - mn1);
            S[j][3] = exp2f(S[j][3] - mn1);
            ls0 += S[j][0] + S[j][1];
            ls1 += S[j][2] + S[j][3];
        }
        ls0 += __shfl_xor_sync(0xffffffffu, ls0, 1);
        ls0 += __shfl_xor_sync(0xffffffffu, ls0, 2);
        ls1 += __shfl_xor_sync(0xffffffffu, ls1, 1);
        ls1 += __shfl_xor_sync(0xffffffffu, ls1, 2);
        l0 = l0 * a0 + ls0;  l1 = l1 * a1 + ls1;
        m0 = mn0;  m1 = mn1;
#pragma unroll
        for (int j = 0; j < 8; ++j) {
            O[j][0] *= a0; O[j][1] *= a0; O[j][2] *= a1; O[j][3] *= a1;
        }

        unsigned pf[4][4];
#pragma unroll
        for (int kc = 0; kc < 4; ++kc) {
            int j0 = 2 * kc, j1 = 2 * kc + 1;
            pf[kc][0] = h2pack(S[j0][0], S[j0][1]);
            pf[kc][1] = h2pack(S[j0][2], S[j0][3]);
            pf[kc][2] = h2pack(S[j1][0], S[j1][1]);
            pf[kc][3] = h2pack(S[j1][2], S[j1][3]);
        }

#pragma unroll
        for (int kc = 0; kc < 4; ++kc) {
#pragma unroll
            for (int pr = 0; pr < 4; ++pr) {
                unsigned t4[4];
                ldsm4t(t4, &Vs[buf][kc * 16 + (lane & 7) + ((lane >> 3) & 1) * 8]
                            [8 * (2 * pr + (lane >> 4))]);
                mma16816(O[2 * pr    ], pf[kc], t4);
                mma16816(O[2 * pr + 1], pf[kc], t4 + 2);
            }
        }
        __syncthreads();
    }

    float i0 = 1.f / l0, i1 = 1.f / l1;
    __half* d0 = g_ctx + ((size_t)(b * Ntok + q0 + 16 * warp + g    )) * Dmod + h * HDim;
    __half* d1 = g_ctx + ((size_t)(b * Ntok + q0 + 16 * warp + 8 + g)) * Dmod + h * HDim;
#pragma unroll
    for (int nj = 0; nj < 8; ++nj) {
        *(__half2*)(d0 + 8 * nj + 2 * tq) = __floats2half2_rn(O[nj][0] * i0, O[nj][1] * i0);
        *(__half2*)(d1 + 8 * nj + 2 * tq) = __floats2half2_rn(O[nj][2] * i1, O[nj][3] * i1);
    }
}

// ---------------------------------------------------------------------------
extern "C" void kernel_launch(void* const* d_in, const int* in_sizes, int n_in,
                              void* d_out, int out_size)
{
    const float* x1 = (const float*)d_in[0];
    const float* x2 = (const float*)d_in[1];
    const float* Wq = (const float*)d_in[2];
    const float* Wk = (const float*)d_in[3];
    const float* Wv = (const float*)d_in[4];
    const float* Wo = (const float*)d_in[5];
    const float* bo = (const float*)d_in[6];
    float* out = (float*)d_out;

    dim3 blk(256);
    dim3 gq (Dmod / GBN, MROWS / GBM);         // (6, 64)
    dim3 gkv(Dmod / GBN, 2 * MROWS / GBM);     // (6, 128)

    gemm_h<<<gq,  blk>>>(x1, nullptr, Wq, nullptr, nullptr, 1);   // Q (scaled)
    gemm_h<<<gkv, blk>>>(x1, x2,      Wk, nullptr, nullptr, 2);   // K (concat)
    gemm_h<<<gkv, blk>>>(x1, x2,      Wv, nullptr, nullptr, 3);   // V (concat)
    attn_h<<<dim3(Ntok / 64, Bsz * Hn), 128>>>();                 // ctx
    gemm_h<<<gq,  blk>>>(nullptr, nullptr, Wo, bo, out, 0);       // out proj
}

// round 11
// speedup vs baseline: 9.5889x; 1.4839x over previous
#include <cuda_runtime.h>
#include <cuda_fp16.h>

// ---------------------------------------------------------------------------
// PairWiseCrossAttention (B=8, N=1024, D=768, H=12, HD=64) — Round 11:
// R10 with ONE change: GEMM blocks use 512 threads (16 warps, 32x32 warp
// tiles) on the same 128x128 tile -> 4 warps/SMSP, 32-reg accumulators,
// no spill. Attention byte-identical (210us measured).
// ---------------------------------------------------------------------------

#define Bsz   8
#define Ntok  1024
#define Dmod  768
#define Hn    12
#define HDim  64
#define N2    2048
#define MROWS 8192

__device__ __half g_Q  [(size_t)Bsz * Hn * Ntok * HDim];
__device__ __half g_K  [(size_t)Bsz * Hn * N2   * HDim];
__device__ __half g_V  [(size_t)Bsz * Hn * N2   * HDim];
__device__ __half g_ctx[(size_t)Bsz * Ntok * Dmod];

#define QSC 0.1803368801111204f   // 0.125 * log2(e): softmax in exp2 domain

__device__ __forceinline__ unsigned smaddr(const void* p) {
    return (unsigned)__cvta_generic_to_shared(p);
}
__device__ __forceinline__ void ldsm4(unsigned* r, const void* p) {
    asm volatile("ldmatrix.sync.aligned.m8n8.x4.shared.b16 {%0,%1,%2,%3},[%4];"
        : "=r"(r[0]), "=r"(r[1]), "=r"(r[2]), "=r"(r[3]) : "r"(smaddr(p)));
}
__device__ __forceinline__ void ldsm4t(unsigned* r, const void* p) {
    asm volatile("ldmatrix.sync.aligned.m8n8.x4.trans.shared.b16 {%0,%1,%2,%3},[%4];"
        : "=r"(r[0]), "=r"(r[1]), "=r"(r[2]), "=r"(r[3]) : "r"(smaddr(p)));
}
__device__ __forceinline__ void mma16816(float* c, const unsigned* a, const unsigned* b) {
    asm volatile("mma.sync.aligned.m16n8k16.row.col.f32.f16.f16.f32 "
        "{%0,%1,%2,%3},{%4,%5,%6,%7},{%8,%9},{%0,%1,%2,%3};"
        : "+f"(c[0]), "+f"(c[1]), "+f"(c[2]), "+f"(c[3])
        : "r"(a[0]), "r"(a[1]), "r"(a[2]), "r"(a[3]), "r"(b[0]), "r"(b[1]));
}
__device__ __forceinline__ unsigned h2pack(float x, float y) {
    __half2 h = __floats2half2_rn(x, y);
    return *(unsigned*)&h;
}
__device__ __forceinline__ void cpasync16(void* dst, const void* src) {
    asm volatile("cp.async.cg.shared.global [%0],[%1],16;" :: "r"(smaddr(dst)), "l"(src));
}

// ---------------------------------------------------------------------------
// GEMM: C = A @ W^T (+bias). 128x128 block, BK=32, 512 threads (16 warps,
// 4x4 warp grid, 32x32 warp tiles). Double-buffered smem, 1 barrier/tile.
// mode 0: A=g_ctx (fp16) -> Cout fp32 + bias
// mode 1: A=x1           -> g_Q heads (scaled by QSC)
// mode 2/3: A=[x1;x2]    -> g_K / g_V heads
// ---------------------------------------------------------------------------
#define GBM 128
#define GBN 128
#define GBK 32
#define AST 40    // smem stride (halves): 80B rows, ldmatrix conflict-free (proven)
#define NKIT 24   // 768/32

// Loader: r = tid>>2 (row 0..127), q = tid&3; thread owns floats [8q,8q+8)
// of its row for both A and B tiles. Prefetch keeps raw float4s (pack at STS).
#define LOAD_REGS(kbase) do {                                                    \
    if (mode == 0) {                                                             \
        pah = *(const uint4*)(Ah + (size_t)(m0 + r) * Dmod + (kbase) + fq);      \
    } else {                                                                     \
        pa0 = *(const float4*)(A + (size_t)(mrow + r) * Dmod + (kbase) + fq);    \
        pa1 = *(const float4*)(A + (size_t)(mrow + r) * Dmod + (kbase) + fq + 4);\
    }                                                                            \
    pb0 = *(const float4*)(W + (size_t)(n0 + r) * Dmod + (kbase) + fq);          \
    pb1 = *(const float4*)(W + (size_t)(n0 + r) * Dmod + (kbase) + fq + 4);      \
} while (0)

#define STS_STAGE(st) do {                                                       \
    if (mode == 0) {                                                             \
        *(uint4*)&As[(st)][r][fq] = pah;                                         \
    } else {                                                                     \
        uint4 wa = { h2pack(pa0.x, pa0.y), h2pack(pa0.z, pa0.w),                 \
                     h2pack(pa1.x, pa1.y), h2pack(pa1.z, pa1.w) };               \
        *(uint4*)&As[(st)][r][fq] = wa;                                          \
    }                                                                            \
    {                                                                            \
        uint4 wb = { h2pack(pb0.x, pb0.y), h2pack(pb0.z, pb0.w),                 \
                     h2pack(pb1.x, pb1.y), h2pack(pb1.z, pb1.w) };               \
        *(uint4*)&Bs[(st)][r][fq] = wb;                                          \
    }                                                                            \
} while (0)

__global__ __launch_bounds__(512)
void gemm_h(const float* __restrict__ A0, const float* __restrict__ A1,
            const float* __restrict__ W,  const float* __restrict__ bias,
            float* __restrict__ Cout, int mode)
{
    __shared__ __half As[2][GBM][AST];
    __shared__ __half Bs[2][GBN][AST];

    const int tid  = threadIdx.x;
    const int lane = tid & 31, warp = tid >> 5;       // warp 0..15
    const int g = lane >> 2, tq = lane & 3;
    const int wm = warp >> 2, wn = warp & 3;          // 4 x 4 warp grid, 32x32 tiles
    const int m0 = blockIdx.y * GBM, n0 = blockIdx.x * GBN;

    const float* A = A0;
    int mrow = m0;
    if ((mode == 2 || mode == 3) && m0 >= MROWS) { A = A1; mrow = m0 - MROWS; }
    const __half* Ah = g_ctx;   // mode 0 source

    const int r  = tid >> 2;          // 0..127
    const int fq = (tid & 3) * 8;     // float/half offset within BK row

    float acc[2][4][4];
#pragma unroll
    for (int i = 0; i < 2; ++i)
#pragma unroll
        for (int j = 0; j < 4; ++j)
#pragma unroll
            for (int c = 0; c < 4; ++c) acc[i][j][c] = 0.f;

    float4 pa0, pa1, pb0, pb1;
    uint4  pah;

    // Prologue: tile 0 -> stage 0; prefetch tile 1 into regs.
    LOAD_REGS(0);
    STS_STAGE(0);
    __syncthreads();
    LOAD_REGS(GBK);

    // Mainloop: tile it in stage it&1; one barrier per iteration.
    for (int it = 0; it < NKIT; ++it) {
        const int cur = it & 1;
        if (it + 1 < NKIT) STS_STAGE(cur ^ 1);          // store tile it+1
        if (it + 2 < NKIT) LOAD_REGS((it + 2) * GBK);   // prefetch tile it+2

#pragma unroll
        for (int ks = 0; ks < 2; ++ks) {
            unsigned af[2][4], bf[4][2];
#pragma unroll
            for (int mi = 0; mi < 2; ++mi)
                ldsm4(af[mi], &As[cur][wm * 32 + mi * 16 + (lane & 15)][ks * 16 + (lane >> 4) * 8]);
#pragma unroll
            for (int pr = 0; pr < 2; ++pr) {
                unsigned t4[4];
                ldsm4(t4, &Bs[cur][wn * 32 + pr * 16 + (lane & 7) + ((lane >> 4) << 3)]
                           [ks * 16 + ((lane >> 3) & 1) * 8]);
                bf[2 * pr    ][0] = t4[0]; bf[2 * pr    ][1] = t4[1];
                bf[2 * pr + 1][0] = t4[2]; bf[2 * pr + 1][1] = t4[3];
            }
#pragma unroll
            for (int mi = 0; mi < 2; ++mi)
#pragma unroll
                for (int nj = 0; nj < 4; ++nj)
                    mma16816(acc[mi][nj], af[mi], bf[nj]);
        }
        __syncthreads();
    }

    // Epilogue (same write logic as R10; warp tile now 32x32)
#pragma unroll
    for (int mi = 0; mi < 2; ++mi) {
#pragma unroll
        for (int rr = 0; rr < 2; ++rr) {
            int gm = m0 + wm * 32 + 16 * mi + g + 8 * rr;
#pragma unroll
            for (int nj = 0; nj < 4; ++nj) {
                int gn = n0 + wn * 32 + 8 * nj + 2 * tq;
                float v0 = acc[mi][nj][2 * rr], v1 = acc[mi][nj][2 * rr + 1];
                if (mode == 0) {
                    float2 o = { v0 + bias[gn], v1 + bias[gn + 1] };
                    *(float2*)(Cout + (size_t)gm * Dmod + gn) = o;
                } else {
                    int hh = gn >> 6, dd = gn & 63;
                    if (mode == 1) {
                        int b = gm >> 10, tok = gm & 1023;
                        *(__half2*)(g_Q + (((size_t)(b * Hn + hh)) * Ntok + tok) * HDim + dd)
                            = __floats2half2_rn(v0 * QSC, v1 * QSC);
                    } else {
                        int b, seq;
                        if (gm < MROWS) { b = gm >> 10; seq = gm & 1023; }
                        else { int m2 = gm - MROWS; b = m2 >> 10; seq = Ntok + (m2 & 1023); }
                        __half* dst = (mode == 2) ? g_K : g_V;
                        *(__half2*)(dst + (((size_t)(b * Hn + hh)) * N2 + seq) * HDim + dd)
                            = __floats2half2_rn(v0, v1);
                    }
                }
            }
        }
    }
}

// ---------------------------------------------------------------------------
// Attention — byte-identical to Round 4/10 (measured ~208-210us).
// ---------------------------------------------------------------------------
#define KST 72

__global__ __launch_bounds__(128)
void attn_h()
{
    __shared__ __half Qs[64][KST];
    __shared__ __half Ks[2][64][KST];
    __shared__ __half Vs[2][64][KST];

    const int t = threadIdx.x, lane = t & 31, warp = t >> 5;
    const int g = lane >> 2, tq = lane & 3;
    const int q0 = blockIdx.x * 64, bh = blockIdx.y;
    const int b = bh / Hn, h = bh - b * Hn;

    const __half* Qg = g_Q + ((size_t)bh * Ntok + q0) * HDim;
    const __half* Kg = g_K + (size_t)bh * N2 * HDim;
    const __half* Vg = g_V + (size_t)bh * N2 * HDim;

    auto issue = [&](int buf, int k0) {
        for (int i = t; i < 512; i += 128) {
            int r = i >> 3, c = (i & 7) * 8;
            cpasync16(&Ks[buf][r][c], Kg + (size_t)(k0 + r) * HDim + c);
            cpasync16(&Vs[buf][r][c], Vg + (size_t)(k0 + r) * HDim + c);
        }
        asm volatile("cp.async.commit_group;");
    };
    issue(0, 0);

    for (int i = t; i < 512; i += 128) {
        int r = i >> 3, c = (i & 7) * 8;
        *(uint4*)&Qs[r][c] = *(const uint4*)(Qg + (size_t)r * HDim + c);
    }
    __syncthreads();

    unsigned qa[4][4];
#pragma unroll
    for (int ks = 0; ks < 4; ++ks)
        ldsm4(qa[ks], &Qs[16 * warp + (lane & 15)][ks * 16 + (lane >> 4) * 8]);

    float m0 = -1e30f, m1 = -1e30f, l0 = 0.f, l1 = 0.f;
    float O[8][4];
#pragma unroll
    for (int j = 0; j < 8; ++j)
#pragma unroll
        for (int c = 0; c < 4; ++c) O[j][c] = 0.f;

    for (int it = 0; it < 32; ++it) {
        const int buf = it & 1;
        if (it < 31) {
            issue(buf ^ 1, (it + 1) * 64);
            asm volatile("cp.async.wait_group 1;");
        } else {
            asm volatile("cp.async.wait_group 0;");
        }
        __syncthreads();

        float S[8][4];
#pragma unroll
        for (int j = 0; j < 8; ++j)
#pragma unroll
            for (int c = 0; c < 4; ++c) S[j][c] = 0.f;
#pragma unroll
        for (int ks = 0; ks < 4; ++ks) {
#pragma unroll
            for (int pr = 0; pr < 4; ++pr) {
                unsigned t4[4];
                ldsm4(t4, &Ks[buf][pr * 16 + (lane & 7) + ((lane >> 4) << 3)]
                           [ks * 16 + ((lane >> 3) & 1) * 8]);
                mma16816(S[2 * pr    ], qa[ks], t4);
                mma16816(S[2 * pr + 1], qa[ks], t4 + 2);
            }
        }

        float mt0 = -1e30f, mt1 = -1e30f;
#pragma unroll
        for (int j = 0; j < 8; ++j) {
            mt0 = fmaxf(mt0, fmaxf(S[j][0], S[j][1]));
            mt1 = fmaxf(mt1, fmaxf(S[j][2], S[j][3]));
        }
        mt0 = fmaxf(mt0, __shfl_xor_sync(0xffffffffu, mt0, 1));
        mt0 = fmaxf(mt0, __shfl_xor_sync(0xffffffffu, mt0, 2));
        mt1 = fmaxf(mt1, __shfl_xor_sync(0xffffffffu, mt1, 1));
        mt1 = fmaxf(mt1, __shfl_xor_sync(0xffffffffu, mt1, 2));
        float mn0 = fmaxf(m0, mt0), mn1 = fmaxf(m1, mt1);
        float a0 = exp2f(m0 - mn0), a1 = exp2f(m1 - mn1);
        float ls0 = 0.f, ls1 = 0.f;
#pragma unroll
        for (int j = 0; j < 8; ++j) {
            S[j][0] = exp2f(S[j][0] - mn0);
            S[j][1] = exp2f(S[j][1] - mn0);
            S[j][2] = exp2f(S[j][2] - mn1);
            S[j][3] = exp2f(S[j][3] - mn1);
            ls0 += S[j][0] + S[j][1];
            ls1 += S[j][2] + S[j][3];
        }
        ls0 += __shfl_xor_sync(0xffffffffu, ls0, 1);
        ls0 += __shfl_xor_sync(0xffffffffu, ls0, 2);
        ls1 += __shfl_xor_sync(0xffffffffu, ls1, 1);
        ls1 += __shfl_xor_sync(0xffffffffu, ls1, 2);
        l0 = l0 * a0 + ls0;  l1 = l1 * a1 + ls1;
        m0 = mn0;  m1 = mn1;
#pragma unroll
        for (int j = 0; j < 8; ++j) {
            O[j][0] *= a0; O[j][1] *= a0; O[j][2] *= a1; O[j][3] *= a1;
        }

        unsigned pf[4][4];
#pragma unroll
        for (int kc = 0; kc < 4; ++kc) {
            int j0 = 2 * kc, j1 = 2 * kc + 1;
            pf[kc][0] = h2pack(S[j0][0], S[j0][1]);
            pf[kc][1] = h2pack(S[j0][2], S[j0][3]);
            pf[kc][2] = h2pack(S[j1][0], S[j1][1]);
            pf[kc][3] = h2pack(S[j1][2], S[j1][3]);
        }

#pragma unroll
        for (int kc = 0; kc < 4; ++kc) {
#pragma unroll
            for (int pr = 0; pr < 4; ++pr) {
                unsigned t4[4];
                ldsm4t(t4, &Vs[buf][kc * 16 + (lane & 7) + ((lane >> 3) & 1) * 8]
                            [8 * (2 * pr + (lane >> 4))]);
                mma16816(O[2 * pr    ], pf[kc], t4);
                mma16816(O[2 * pr + 1], pf[kc], t4 + 2);
            }
        }
        __syncthreads();
    }

    float i0 = 1.f / l0, i1 = 1.f / l1;
    __half* d0 = g_ctx + ((size_t)(b * Ntok + q0 + 16 * warp + g    )) * Dmod + h * HDim;
    __half* d1 = g_ctx + ((size_t)(b * Ntok + q0 + 16 * warp + 8 + g)) * Dmod + h * HDim;
#pragma unroll
    for (int nj = 0; nj < 8; ++nj) {
        *(__half2*)(d0 + 8 * nj + 2 * tq) = __floats2half2_rn(O[nj][0] * i0, O[nj][1] * i0);
        *(__half2*)(d1 + 8 * nj + 2 * tq) = __floats2half2_rn(O[nj][2] * i1, O[nj][3] * i1);
    }
}

// ---------------------------------------------------------------------------
extern "C" void kernel_launch(void* const* d_in, const int* in_sizes, int n_in,
                              void* d_out, int out_size)
{
    const float* x1 = (const float*)d_in[0];
    const float* x2 = (const float*)d_in[1];
    const float* Wq = (const float*)d_in[2];
    const float* Wk = (const float*)d_in[3];
    const float* Wv = (const float*)d_in[4];
    const float* Wo = (const float*)d_in[5];
    const float* bo = (const float*)d_in[6];
    float* out = (float*)d_out;

    dim3 blk(512);
    dim3 gq (Dmod / GBN, MROWS / GBM);         // (6, 64)
    dim3 gkv(Dmod / GBN, 2 * MROWS / GBM);     // (6, 128)

    gemm_h<<<gq,  blk>>>(x1, nullptr, Wq, nullptr, nullptr, 1);   // Q (scaled)
    gemm_h<<<gkv, blk>>>(x1, x2,      Wk, nullptr, nullptr, 2);   // K (concat)
    gemm_h<<<gkv, blk>>>(x1, x2,      Wv, nullptr, nullptr, 3);   // V (concat)
    attn_h<<<dim3(Ntok / 64, Bsz * Hn), 128>>>();                 // ctx
    gemm_h<<<gq,  blk>>>(nullptr, nullptr, Wo, bo, out, 0);       // out proj
}